// round 10
// baseline (speedup 1.0000x reference)
#include <cuda_runtime.h>
#include <stdint.h>

#define B_    32
#define HW_   225
#define C_    128
#define OUTH  7
#define OUTW  7
#define ITERS 10
#define NS    4                     // row-chunk splits per pooled cell
#define NPOOLBLK (B_ * 64 * NS)     // 8192 pool blocks
#define NCOMBBLK 196                // 50176 outputs / 256 threads

// Partial maxes: [NS][B][8*8 cells][128 ch] = 4 MB device scratch
__device__ float g_part[NS * B_ * 64 * C_];
__device__ unsigned int g_pool_done;   // zero-init; reset each call by last combine block
__device__ unsigned int g_comb_done;

__device__ __forceinline__ float4 fmax4(float4 a, float4 b) {
    return make_float4(fmaxf(a.x, b.x), fmaxf(a.y, b.y),
                       fmaxf(a.z, b.z), fmaxf(a.w, b.w));
}
__device__ __forceinline__ float neg_inf() { return __int_as_float(0xff800000); }
__device__ __forceinline__ float4 neg4() {
    return make_float4(neg_inf(), neg_inf(), neg_inf(), neg_inf());
}

struct IdxPack { int ii[ITERS]; int jj[ITERS]; };

// -----------------------------------------------------------------------------
// Fused kernel, register-capped: __launch_bounds__(256, 6) forces <=42 regs so
// the POOL path keeps 6 blocks/SM (1536 threads) — the R7 fusion lost 8% HBM BW
// because unified allocation hit 59 regs / 4 blocks/SM. The combine path may
// spill a little to local; it runs in the pool's tail shadow on hot L2.
//
// Blocks [0, NPOOLBLK): partial max pool.
//   Window = stride = 32, SAME padding (pad_lo=15, pad_hi=16) -> disjoint.
//   lane -> channel quad (512B contiguous per pixel), rg -> row within chunk.
// Blocks [NPOOLBLK, ...): spin on g_pool_done (threadfence-reduction pattern),
//   then NS-reduce partials + 10-iteration merge/average. Last combine block
//   resets counters so every graph replay starts from identical state.
// -----------------------------------------------------------------------------
__global__ void __launch_bounds__(256, 6) fused_kernel(const float* __restrict__ x,
                                                       float* __restrict__ out,
                                                       IdxPack ip) {
    const int bid = blockIdx.x;
    const int tid = threadIdx.x;

    if (bid < NPOOLBLK) {
        // ---------------- pool path ----------------
        const int b    = bid >> 8;           // 0..31
        const int cell = (bid >> 2) & 63;    // 0..63
        const int s    = bid & (NS - 1);     // 0..3
        const int i = cell >> 3, j = cell & 7;

        int h0 = i * 32 - 15; if (h0 < 0)   h0 = 0;
        int h1 = i * 32 + 17; if (h1 > HW_) h1 = HW_;
        int w0 = j * 32 - 15; if (w0 < 0)   w0 = 0;
        int w1 = j * 32 + 17; if (w1 > HW_) w1 = HW_;
        const int nw = w1 - w0;

        const int lane = tid & 31;
        const int rg   = tid >> 5;
        const int h    = h0 + s * 8 + rg;

        float4 a0 = neg4(), a1 = neg4(), a2 = neg4(), a3 = neg4();

        if (h < h1) {
            const float4* __restrict__ p =
                (const float4*)x + ((size_t)((b * HW_ + h) * HW_ + w0)) * 32 + lane;
            if (nw == 32) {
                #pragma unroll
                for (int k = 0; k < 8; ++k) {
                    a0 = fmax4(a0, __ldcs(p + (k * 4 + 0) * 32));
                    a1 = fmax4(a1, __ldcs(p + (k * 4 + 1) * 32));
                    a2 = fmax4(a2, __ldcs(p + (k * 4 + 2) * 32));
                    a3 = fmax4(a3, __ldcs(p + (k * 4 + 3) * 32));
                }
            } else {
                int w = 0;
                for (; w + 4 <= nw; w += 4) {
                    a0 = fmax4(a0, __ldcs(p + (w + 0) * 32));
                    a1 = fmax4(a1, __ldcs(p + (w + 1) * 32));
                    a2 = fmax4(a2, __ldcs(p + (w + 2) * 32));
                    a3 = fmax4(a3, __ldcs(p + (w + 3) * 32));
                }
                for (; w < nw; ++w) a0 = fmax4(a0, __ldcs(p + w * 32));
            }
        }
        float4 acc = fmax4(fmax4(a0, a1), fmax4(a2, a3));

        __shared__ float4 part[8][32];
        part[rg][lane] = acc;
        __syncthreads();

        if (rg == 0) {
            float4 m = part[0][lane];
            #pragma unroll
            for (int k = 1; k < 8; ++k) m = fmax4(m, part[k][lane]);
            ((float4*)g_part)[((s * B_ + b) * 64 + cell) * 32 + lane] = m;
        }

        // release: all threads fence, then one atomic increments the done count
        __threadfence();
        __syncthreads();
        if (tid == 0) atomicAdd(&g_pool_done, 1u);

    } else {
        // ---------------- combine path ----------------
        if (tid == 0) {
            while (*((volatile unsigned int*)&g_pool_done) != (unsigned)NPOOLBLK)
                __nanosleep(64);
        }
        __syncthreads();
        __threadfence();   // acquire: order g_part loads after the flag read

        const int t = (bid - NPOOLBLK) * 256 + tid;   // [0, 50176), exact fit

        const int q     = t & 31;
        const int cellc = t >> 5;
        const int c = cellc % OUTW;
        const int r = (cellc / OUTW) % OUTH;
        const int b = cellc / (OUTW * OUTH);

        const float4* __restrict__ P = (const float4*)g_part;

        // include pooled row rr iff rr<=mi, rr+1 iff rr>=mi (cols symmetric)
        float4 p00 = neg4(), p01 = neg4(), p10 = neg4(), p11 = neg4();
        #pragma unroll
        for (int sp = 0; sp < NS; ++sp) {
            const int base = (sp * B_ + b) * 64;
            float4 v0 = __ldg(&P[(base + (r    ) * 8 + c    ) * 32 + q]);
            float4 v1 = __ldg(&P[(base + (r    ) * 8 + c + 1) * 32 + q]);
            float4 v2 = __ldg(&P[(base + (r + 1) * 8 + c    ) * 32 + q]);
            float4 v3 = __ldg(&P[(base + (r + 1) * 8 + c + 1) * 32 + q]);
            p00 = fmax4(p00, v0);
            p01 = fmax4(p01, v1);
            p10 = fmax4(p10, v2);
            p11 = fmax4(p11, v3);
        }

        float4 sum = make_float4(0.f, 0.f, 0.f, 0.f);
        #pragma unroll
        for (int it = 0; it < ITERS; ++it) {
            const int mi = ip.ii[it], mj = ip.jj[it];
            const bool r0 = (r <= mi), r1 = (r >= mi);
            const bool c0 = (c <= mj), c1 = (c >= mj);
            float4 w = neg4();
            if (r0 && c0) w = fmax4(w, p00);
            if (r0 && c1) w = fmax4(w, p01);
            if (r1 && c0) w = fmax4(w, p10);
            if (r1 && c1) w = fmax4(w, p11);
            sum.x += w.x; sum.y += w.y; sum.z += w.z; sum.w += w.w;
        }

        ((float4*)out)[t] = make_float4(sum.x / (float)ITERS, sum.y / (float)ITERS,
                                        sum.z / (float)ITERS, sum.w / (float)ITERS);

        // reset counters for the next (graph-replayed) call — deterministic state
        __threadfence();
        __syncthreads();
        if (tid == 0) {
            unsigned int old = atomicAdd(&g_comb_done, 1u);
            if (old == (unsigned)(NCOMBBLK - 1)) {
                g_pool_done = 0u;
                g_comb_done = 0u;
            }
        }
    }
}

// -----------------------------------------------------------------------------
// Host: exact replication of np.random.RandomState(seed).randint(0, 7)
// Legacy path: init_genrand seeding; bounded draw uses the 32-bit generator
// with masked rejection (mask=7, reject value 7).
// -----------------------------------------------------------------------------
namespace {
struct MT19937 {
    uint32_t mt[624];
    int idx;
    explicit MT19937(uint32_t s) {
        mt[0] = s;
        for (uint32_t k = 1; k < 624; ++k)
            mt[k] = 1812433253u * (mt[k - 1] ^ (mt[k - 1] >> 30)) + k;
        idx = 624;
    }
    uint32_t next() {
        if (idx >= 624) {
            for (int k = 0; k < 624; ++k) {
                uint32_t y = (mt[k] & 0x80000000u) | (mt[(k + 1) % 624] & 0x7fffffffu);
                uint32_t v = mt[(k + 397) % 624] ^ (y >> 1);
                if (y & 1u) v ^= 0x9908b0dfu;
                mt[k] = v;
            }
            idx = 0;
        }
        uint32_t y = mt[idx++];
        y ^= y >> 11;
        y ^= (y << 7)  & 0x9d2c5680u;
        y ^= (y << 15) & 0xefc60000u;
        y ^= y >> 18;
        return y;
    }
    int randint7() {    // randint(0, 7): masked rejection, mask=7, reject 7
        for (;;) {
            uint32_t v = next() & 7u;
            if (v <= 6u) return (int)v;
        }
    }
};
}  // namespace

extern "C" void kernel_launch(void* const* d_in, const int* in_sizes, int n_in,
                              void* d_out, int out_size) {
    const float* x = (const float*)d_in[0];
    float* out     = (float*)d_out;

    IdxPack ip;
    for (int it = 0; it < ITERS; ++it) {
        MT19937 m(42u + (uint32_t)it);
        ip.ii[it] = m.randint7();
        ip.jj[it] = m.randint7();
    }

    fused_kernel<<<NPOOLBLK + NCOMBBLK, 256>>>(x, out, ip);
}

// round 11
// speedup vs baseline: 1.1147x; 1.1147x over previous
#include <cuda_runtime.h>
#include <stdint.h>

#define B_    32
#define HW_   225
#define C_    128
#define OUTH  7
#define OUTW  7
#define ITERS 10
#define NS    4                     // row-chunk splits per pooled cell
#define NPOOLBLK (B_ * 64 * NS)     // 8192 pool blocks
#define NCOMBBLK 196                // 50176 outputs / 256 threads

// Partial maxes: [NS][B][8*8 cells][128 ch] = 4 MB device scratch
__device__ float g_part[NS * B_ * 64 * C_];
__device__ unsigned int g_pool_done;   // zero-init; reset each call by last combine block
__device__ unsigned int g_comb_done;

__device__ __forceinline__ float4 fmax4(float4 a, float4 b) {
    return make_float4(fmaxf(a.x, b.x), fmaxf(a.y, b.y),
                       fmaxf(a.z, b.z), fmaxf(a.w, b.w));
}
__device__ __forceinline__ float neg_inf() { return __int_as_float(0xff800000); }
__device__ __forceinline__ float4 neg4() {
    return make_float4(neg_inf(), neg_inf(), neg_inf(), neg_inf());
}

// Release-increment at gpu scope: publishes this CTA's prior (bar-synchronized)
// writes WITHOUT membar.gl — avoids the per-block CCTL.IVALL L1D flush that
// cost ~8% HBM bandwidth in R7/R9 (all-thread __threadfence).
__device__ __forceinline__ void signal_release(unsigned int* ctr) {
    asm volatile("red.release.gpu.global.add.u32 [%0], 1;"
                 :: "l"(ctr) : "memory");
}
__device__ __forceinline__ unsigned int load_acquire(const unsigned int* ctr) {
    unsigned int v;
    asm volatile("ld.acquire.gpu.global.u32 %0, [%1];"
                 : "=r"(v) : "l"(ctr) : "memory");
    return v;
}

struct IdxPack { int ii[ITERS]; int jj[ITERS]; };

// -----------------------------------------------------------------------------
// Fused kernel.
// Blocks [0, NPOOLBLK): partial max pool.
//   Window = stride = 32, SAME padding (pad_lo=15, pad_hi=16) -> disjoint.
//   lane -> channel quad (512B contiguous per pixel), rg -> row within chunk.
//   Exit: stores -> __syncthreads (CTA-cumulative) -> tid0 red.release.gpu.
// Blocks [NPOOLBLK, ...): tid0 spins on ld.acquire.gpu until all pool blocks
//   have signalled, __syncthreads propagates, then NS-reduce + 10-iter merge.
//   Last combine block resets both counters so every graph replay starts from
//   identical state (kernel completion orders the reset for the next replay).
// -----------------------------------------------------------------------------
__global__ void __launch_bounds__(256) fused_kernel(const float* __restrict__ x,
                                                    float* __restrict__ out,
                                                    IdxPack ip) {
    const int bid = blockIdx.x;
    const int tid = threadIdx.x;

    if (bid < NPOOLBLK) {
        // ---------------- pool path ----------------
        const int b    = bid >> 8;           // 0..31
        const int cell = (bid >> 2) & 63;    // 0..63
        const int s    = bid & (NS - 1);     // 0..3
        const int i = cell >> 3, j = cell & 7;

        int h0 = i * 32 - 15; if (h0 < 0)   h0 = 0;
        int h1 = i * 32 + 17; if (h1 > HW_) h1 = HW_;
        int w0 = j * 32 - 15; if (w0 < 0)   w0 = 0;
        int w1 = j * 32 + 17; if (w1 > HW_) w1 = HW_;
        const int nw = w1 - w0;

        const int lane = tid & 31;
        const int rg   = tid >> 5;
        const int h    = h0 + s * 8 + rg;

        float4 a0 = neg4(), a1 = neg4(), a2 = neg4(), a3 = neg4();

        if (h < h1) {
            const float4* __restrict__ p =
                (const float4*)x + ((size_t)((b * HW_ + h) * HW_ + w0)) * 32 + lane;
            if (nw == 32) {
                #pragma unroll
                for (int k = 0; k < 8; ++k) {
                    a0 = fmax4(a0, __ldcs(p + (k * 4 + 0) * 32));
                    a1 = fmax4(a1, __ldcs(p + (k * 4 + 1) * 32));
                    a2 = fmax4(a2, __ldcs(p + (k * 4 + 2) * 32));
                    a3 = fmax4(a3, __ldcs(p + (k * 4 + 3) * 32));
                }
            } else {
                int w = 0;
                for (; w + 4 <= nw; w += 4) {
                    a0 = fmax4(a0, __ldcs(p + (w + 0) * 32));
                    a1 = fmax4(a1, __ldcs(p + (w + 1) * 32));
                    a2 = fmax4(a2, __ldcs(p + (w + 2) * 32));
                    a3 = fmax4(a3, __ldcs(p + (w + 3) * 32));
                }
                for (; w < nw; ++w) a0 = fmax4(a0, __ldcs(p + w * 32));
            }
        }
        float4 acc = fmax4(fmax4(a0, a1), fmax4(a2, a3));

        __shared__ float4 part[8][32];
        part[rg][lane] = acc;
        __syncthreads();

        if (rg == 0) {
            float4 m = part[0][lane];
            #pragma unroll
            for (int k = 1; k < 8; ++k) m = fmax4(m, part[k][lane]);
            ((float4*)g_part)[((s * B_ + b) * 64 + cell) * 32 + lane] = m;
        }

        // release: bar.sync makes warp0's stores CTA-visible (cumulative),
        // then one release-atomic publishes them at gpu scope. No membar.gl.
        __syncthreads();
        if (tid == 0) signal_release(&g_pool_done);

    } else {
        // ---------------- combine path ----------------
        if (tid == 0) {
            while (load_acquire(&g_pool_done) != (unsigned)NPOOLBLK)
                __nanosleep(64);
        }
        __syncthreads();   // propagate tid0's acquire CTA-wide

        const int t = (bid - NPOOLBLK) * 256 + tid;   // [0, 50176), exact fit

        const int q     = t & 31;
        const int cellc = t >> 5;
        const int c = cellc % OUTW;
        const int r = (cellc / OUTW) % OUTH;
        const int b = cellc / (OUTW * OUTH);

        const float4* __restrict__ P = (const float4*)g_part;

        // include pooled row rr iff rr<=mi, rr+1 iff rr>=mi (cols symmetric)
        float4 p00 = neg4(), p01 = neg4(), p10 = neg4(), p11 = neg4();
        #pragma unroll
        for (int sp = 0; sp < NS; ++sp) {
            const int base = (sp * B_ + b) * 64;
            float4 v0 = P[(base + (r    ) * 8 + c    ) * 32 + q];
            float4 v1 = P[(base + (r    ) * 8 + c + 1) * 32 + q];
            float4 v2 = P[(base + (r + 1) * 8 + c    ) * 32 + q];
            float4 v3 = P[(base + (r + 1) * 8 + c + 1) * 32 + q];
            p00 = fmax4(p00, v0);
            p01 = fmax4(p01, v1);
            p10 = fmax4(p10, v2);
            p11 = fmax4(p11, v3);
        }

        float4 sum = make_float4(0.f, 0.f, 0.f, 0.f);
        #pragma unroll
        for (int it = 0; it < ITERS; ++it) {
            const int mi = ip.ii[it], mj = ip.jj[it];
            const bool r0 = (r <= mi), r1 = (r >= mi);
            const bool c0 = (c <= mj), c1 = (c >= mj);
            float4 w = neg4();
            if (r0 && c0) w = fmax4(w, p00);
            if (r0 && c1) w = fmax4(w, p01);
            if (r1 && c0) w = fmax4(w, p10);
            if (r1 && c1) w = fmax4(w, p11);
            sum.x += w.x; sum.y += w.y; sum.z += w.z; sum.w += w.w;
        }

        ((float4*)out)[t] = make_float4(sum.x / (float)ITERS, sum.y / (float)ITERS,
                                        sum.z / (float)ITERS, sum.w / (float)ITERS);

        // reset counters for the next graph replay — deterministic state.
        // Kernel completion orders these writes before the next launch.
        __syncthreads();
        if (tid == 0) {
            unsigned int old;
            asm volatile("atom.acq_rel.gpu.global.add.u32 %0, [%1], 1;"
                         : "=r"(old) : "l"(&g_comb_done) : "memory");
            if (old == (unsigned)(NCOMBBLK - 1)) {
                g_pool_done = 0u;
                g_comb_done = 0u;
            }
        }
    }
}

// -----------------------------------------------------------------------------
// Host: exact replication of np.random.RandomState(seed).randint(0, 7)
// Legacy path: init_genrand seeding; bounded draw uses the 32-bit generator
// with masked rejection (mask=7, reject value 7).
// -----------------------------------------------------------------------------
namespace {
struct MT19937 {
    uint32_t mt[624];
    int idx;
    explicit MT19937(uint32_t s) {
        mt[0] = s;
        for (uint32_t k = 1; k < 624; ++k)
            mt[k] = 1812433253u * (mt[k - 1] ^ (mt[k - 1] >> 30)) + k;
        idx = 624;
    }
    uint32_t next() {
        if (idx >= 624) {
            for (int k = 0; k < 624; ++k) {
                uint32_t y = (mt[k] & 0x80000000u) | (mt[(k + 1) % 624] & 0x7fffffffu);
                uint32_t v = mt[(k + 397) % 624] ^ (y >> 1);
                if (y & 1u) v ^= 0x9908b0dfu;
                mt[k] = v;
            }
            idx = 0;
        }
        uint32_t y = mt[idx++];
        y ^= y >> 11;
        y ^= (y << 7)  & 0x9d2c5680u;
        y ^= (y << 15) & 0xefc60000u;
        y ^= y >> 18;
        return y;
    }
    int randint7() {    // randint(0, 7): masked rejection, mask=7, reject 7
        for (;;) {
            uint32_t v = next() & 7u;
            if (v <= 6u) return (int)v;
        }
    }
};
}  // namespace

extern "C" void kernel_launch(void* const* d_in, const int* in_sizes, int n_in,
                              void* d_out, int out_size) {
    const float* x = (const float*)d_in[0];
    float* out     = (float*)d_out;

    IdxPack ip;
    for (int it = 0; it < ITERS; ++it) {
        MT19937 m(42u + (uint32_t)it);
        ip.ii[it] = m.randint7();
        ip.jj[it] = m.randint7();
    }

    fused_kernel<<<NPOOLBLK + NCOMBBLK, 256>>>(x, out, ip);
}